// round 6
// baseline (speedup 1.0000x reference)
#include <cuda_runtime.h>
#include <cuda_bf16.h>
#include <cstdint>

typedef unsigned long long ull;

// ---------------- scratch (device globals: allocation-free) ----------------
__device__ float g_xw[(size_t)64 * 1024 * 1536];   // 402 MB input projections
__device__ float g_h0[64 * 512];
__device__ float g_h1[64 * 512];
__device__ unsigned g_ctr[8 * 32];                 // fallback: per-bg counters, 128B apart

// ---------------- f32x2 helpers ----------------
__device__ __forceinline__ void fma2(ull& d, ull a, ull b) {
    asm("fma.rn.f32x2 %0, %1, %2, %0;" : "+l"(d) : "l"(a), "l"(b));
}
__device__ __forceinline__ ull splat2(float x) {
    ull r; asm("mov.b64 %0, {%1, %1};" : "=l"(r) : "f"(x)); return r;
}
__device__ __forceinline__ ull pack2(float x, float y) {
    ull r; asm("mov.b64 %0, {%1, %2};" : "=l"(r) : "f"(x), "f"(y)); return r;
}
__device__ __forceinline__ void f4_to_u2(float4 v, ull& a, ull& b) {
    asm("mov.b64 %0, {%1, %2};" : "=l"(a) : "f"(v.x), "f"(v.y));
    asm("mov.b64 %0, {%1, %2};" : "=l"(b) : "f"(v.z), "f"(v.w));
}
__device__ __forceinline__ float2 unpk(ull v) {
    float2 r; asm("mov.b64 {%0, %1}, %2;" : "=f"(r.x), "=f"(r.y) : "l"(v)); return r;
}
__device__ __forceinline__ uint32_t smem_u32(const void* p) {
    uint32_t a;
    asm("{ .reg .u64 t; cvta.to.shared.u64 t, %1; cvt.u32.u64 %0, t; }" : "=r"(a) : "l"(p));
    return a;
}

__device__ __forceinline__ float sigf(float x) {
    return __fdividef(1.0f, 1.0f + __expf(-x));
}
__device__ __forceinline__ float tanh_acc(float x) {
    float ax = fabsf(x);
    float e = __expf(-2.0f * ax);
    float r = __fdividef(1.0f - e, 1.0f + e);
    return copysignf(r, x);
}

// ============================================================================
// Phase 1: xw = x @ W + b_in    (M=65536, K=512, N=1536), f32x2 SGEMM
// ============================================================================
#define P1_BM 128
#define P1_BN 256
#define P1_BK 16

__global__ void __launch_bounds__(256, 1) gemm_xw_kernel(
    const float* __restrict__ A,
    const float* __restrict__ W,
    const float* __restrict__ bias,
    float* __restrict__ C)
{
    __shared__ float As[P1_BK * (P1_BM + 4)];
    __shared__ float Bs[P1_BK * P1_BN];

    const int tid = threadIdx.x;
    const int tx = tid & 15;
    const int ty = tid >> 4;
    const int bm = blockIdx.y * P1_BM;
    const int bn = blockIdx.x * P1_BN;

    ull acc[8][8];
#pragma unroll
    for (int m = 0; m < 8; m++)
#pragma unroll
        for (int g = 0; g < 8; g++) acc[m][g] = 0ull;

    for (int kk = 0; kk < 512; kk += P1_BK) {
#pragma unroll
        for (int i = 0; i < 2; i++) {
            int s = tid + i * 256;
            int m = s >> 2;
            int kq = (s & 3) << 2;
            float4 v = *(const float4*)(A + (size_t)(bm + m) * 512 + kk + kq);
            As[(kq + 0) * (P1_BM + 4) + m] = v.x;
            As[(kq + 1) * (P1_BM + 4) + m] = v.y;
            As[(kq + 2) * (P1_BM + 4) + m] = v.z;
            As[(kq + 3) * (P1_BM + 4) + m] = v.w;
        }
#pragma unroll
        for (int i = 0; i < 4; i++) {
            int s = tid + i * 256;
            int k = s >> 6;
            int n4 = (s & 63) << 2;
            float4 v = *(const float4*)(W + (size_t)(kk + k) * 1536 + bn + n4);
            *(float4*)(Bs + k * P1_BN + n4) = v;
        }
        __syncthreads();

#pragma unroll
        for (int k = 0; k < P1_BK; k++) {
            float4 a0 = *(const float4*)(As + k * (P1_BM + 4) + ty * 8);
            float4 a1 = *(const float4*)(As + k * (P1_BM + 4) + ty * 8 + 4);
            ull bp[8];
#pragma unroll
            for (int g = 0; g < 4; g++) {
                float4 b4 = *(const float4*)(Bs + k * P1_BN + tx * 4 + 64 * g);
                f4_to_u2(b4, bp[2 * g], bp[2 * g + 1]);
            }
            float am[8] = {a0.x, a0.y, a0.z, a0.w, a1.x, a1.y, a1.z, a1.w};
#pragma unroll
            for (int m = 0; m < 8; m++) {
                ull as = splat2(am[m]);
#pragma unroll
                for (int g = 0; g < 8; g++) fma2(acc[m][g], as, bp[g]);
            }
        }
        __syncthreads();
    }

    float4 bi[4];
#pragma unroll
    for (int g = 0; g < 4; g++)
        bi[g] = *(const float4*)(bias + bn + tx * 4 + 64 * g);
#pragma unroll
    for (int m = 0; m < 8; m++) {
        float* crow = C + (size_t)(bm + ty * 8 + m) * 1536;
#pragma unroll
        for (int g = 0; g < 4; g++) {
            float2 p0 = unpk(acc[m][2 * g]);
            float2 p1 = unpk(acc[m][2 * g + 1]);
            float4 o;
            o.x = p0.x + bi[g].x; o.y = p0.y + bi[g].y;
            o.z = p1.x + bi[g].z; o.w = p1.y + bi[g].w;
            *(float4*)(crow + bn + tx * 4 + 64 * g) = o;
        }
    }
}

// ============================================================================
// Phase 2: GRU recurrence, 128 CTAs = 8 batch-groups x 16 unit-groups.
//   All shared state in DYNAMIC smem (58.4 KB > 48 KB static limit).
//   Cluster mode: h exchanged by DSMEM push into peers' double buffer +
//   remote release-arrive; consumer does one acquire try_wait.
//   Fallback: global counter + L2 staging (hs[0] only).
// ============================================================================
#define NB2 128
// dynamic smem layout (floats)
#define OFF_HS   0                 // hs[2][4096]  -> 8192 floats
#define OFF_RED  8192              // red[256*25]  -> 6400 floats
#define OFF_MBAR 14592             // ull mbar     -> 2 floats
#define SM2_FLOATS 14596
#define SM2_BYTES (SM2_FLOATS * 4)

__global__ void __launch_bounds__(256, 1) gru_seq_kernel(
    const float* __restrict__ xw,    // [65536, 1536]  (b*1024+t major)
    const float* __restrict__ rk,    // [512, 1536]
    const float* __restrict__ bias,  // [2, 1536] (row 1 = b_rec)
    float* __restrict__ out,         // [64, 1024, 512]
    float* __restrict__ h0buf,
    float* __restrict__ h1buf,
    unsigned* __restrict__ ctr,
    int use_cluster)
{
    extern __shared__ float sm[];
    float* hs  = sm + OFF_HS;            // [buf*4096 + b*512 + k]
    float* red = sm + OFF_RED;           // (25 = pad, coprime 32)
    ull* mbar  = (ull*)(sm + OFF_MBAR);

    const int tid = threadIdx.x;
    const int bgid = blockIdx.x >> 4;    // 0..7  (cluster id in cluster mode)
    const int ugid = blockIdx.x & 15;    // 0..15 (cluster rank)
    const int u0 = ugid * 32;
    const int b0 = bgid * 8;

    const int w  = tid >> 5;             // warp: GEMM k-chunk / epilogue batch
    const int uu = tid & 31;             // lane: unit within group

    const uint32_t mb = smem_u32(mbar);
    const uint32_t hs_b = smem_u32(hs);

    if (use_cluster) {
        for (int i = tid; i < 4096; i += 256) hs[i] = 0.0f;   // h^0 = 0
        if (tid == 0) {
            asm volatile("mbarrier.init.shared.b64 [%0], 16;" :: "r"(mb) : "memory");
        }
        __syncthreads();
        asm volatile("barrier.cluster.arrive.aligned;" ::: "memory");
        asm volatile("barrier.cluster.wait.aligned;" ::: "memory");
    }

    // ---- load R slice into registers: unit u0+uu, k in [w*64, w*64+64) ----
    ull Rz[32], Rr[32], Rh[32];
    {
        const float* rbase = rk + u0 + uu;
#pragma unroll
        for (int i = 0; i < 32; i++) {
            int k = w * 64 + 2 * i;
            const float* r0 = rbase + (size_t)k * 1536;
            const float* r1 = r0 + 1536;
            Rz[i] = pack2(r0[0],    r1[0]);
            Rr[i] = pack2(r0[512],  r1[512]);
            Rh[i] = pack2(r0[1024], r1[1024]);
        }
    }
    const float bz  = bias[1536 + u0 + uu];
    const float brr = bias[1536 + 512 + u0 + uu];
    const float bh  = bias[1536 + 1024 + u0 + uu];

    const int bglob = b0 + w;                                 // epilogue batch
    const float* xwp = xw + (size_t)bglob * 1024 * 1536 + u0 + uu;
    float* outp = out + (size_t)bglob * 524288 + u0 + uu;
    unsigned* myctr = ctr + bgid * 32;

    float hn_prev = 0.0f;   // h[bglob][u0+uu] carried in-register

    for (int t = 0; t < 1024; t++) {
        // prefetch gate inputs (independent of h)
        const float* xr_ = xwp + (size_t)t * 1536;
        float xz = __ldg(xr_);
        float xr = __ldg(xr_ + 512);
        float xh = __ldg(xr_ + 1024);

        const float* hbuf;

        if (use_cluster) {
            hbuf = hs + (t & 1) * 4096;
            if (t > 0) {
                // all threads wait: acquire gives each thread visibility of
                // the DSMEM-pushed h; no block barrier needed afterwards.
                unsigned parity = (unsigned)((t - 1) & 1);
                uint32_t done;
                do {
                    asm volatile(
                        "{\n\t.reg .pred p;\n\t"
                        "mbarrier.try_wait.parity.acquire.cluster.shared::cta.b64 p, [%1], %2, 0x989680;\n\t"
                        "selp.b32 %0, 1, 0, p;\n\t}"
                        : "=r"(done) : "r"(mb), "r"(parity) : "memory");
                } while (!done);
            }
        } else {
            hbuf = hs;
            const float* hin = (t & 1) ? h1buf : h0buf;
            if (t > 0) {
                if (tid == 0) {
                    unsigned target = (unsigned)(16 * t);
                    unsigned v;
                    do {
                        asm volatile("ld.acquire.gpu.global.u32 %0, [%1];"
                                     : "=r"(v) : "l"(myctr) : "memory");
                    } while (v < target);
                }
                __syncthreads();
            }
#pragma unroll
            for (int i = 0; i < 4; i++) {
                int s = i * 32 + uu;
                int b = s >> 4;
                int j4 = s & 15;
                float4 v = __ldcg((const float4*)(hin + (b0 + b) * 512 + w * 64) + j4);
                *(float4*)(hs + b * 512 + w * 64 + j4 * 4) = v;
            }
            __syncwarp();
        }

        // ---- GEMM partials: warp w, k-chunk [w*64, w*64+64) ----
#pragma unroll 1
        for (int b = 0; b < 8; b++) {
            ull az = 0ull, ar = 0ull, ah = 0ull;
            const float4* hp = (const float4*)(hbuf + b * 512 + w * 64);
#pragma unroll
            for (int q = 0; q < 16; q++) {
                float4 h4 = hp[q];                 // broadcast across warp
                ull h01, h23;
                f4_to_u2(h4, h01, h23);
                fma2(az, h01, Rz[2 * q]); fma2(az, h23, Rz[2 * q + 1]);
                fma2(ar, h01, Rr[2 * q]); fma2(ar, h23, Rr[2 * q + 1]);
                fma2(ah, h01, Rh[2 * q]); fma2(ah, h23, Rh[2 * q + 1]);
            }
            float2 pz = unpk(az), pr = unpk(ar), ph = unpk(ah);
            float* rb = red + (b * 32 + uu) * 25 + w * 3;
            rb[0] = pz.x + pz.y;
            rb[1] = pr.x + pr.y;
            rb[2] = ph.x + ph.y;
        }
        __syncthreads();

        // ---- gates: thread = (batch w, unit uu) ----
        float rz = bz, rr = brr, rh = bh;
        const float* rb = red + (w * 32 + uu) * 25;
#pragma unroll
        for (int s = 0; s < 8; s++) {
            rz += rb[s * 3 + 0];
            rr += rb[s * 3 + 1];
            rh += rb[s * 3 + 2];
        }
        float z  = sigf(xz + rz);
        float r  = sigf(xr + rr);
        float hh = tanh_acc(xh + r * rh);
        float hn = z * hn_prev + (1.0f - z) * hh;
        hn_prev = hn;

        if (use_cluster) {
            // ---- DSMEM scatter: push hn into buf[(t+1)&1] of all 16 peers ----
            uint32_t laddr = hs_b +
                ((((t + 1) & 1) << 12) + (w << 9) + u0 + uu) * 4u;
#pragma unroll
            for (int rnk = 0; rnk < 16; rnk++) {
                uint32_t ra;
                asm("mapa.shared::cluster.u32 %0, %1, %2;" : "=r"(ra)
                    : "r"(laddr), "r"(rnk));
                asm volatile("st.shared::cluster.f32 [%0], %1;"
                             :: "r"(ra), "f"(hn) : "memory");
            }
            __syncthreads();   // all scatter stores done before the arrives
            if (tid < 16) {
                uint32_t ra;
                asm("mapa.shared::cluster.u32 %0, %1, %2;" : "=r"(ra)
                    : "r"(mb), "r"(tid));
                asm volatile(
                    "mbarrier.arrive.release.cluster.shared::cluster.b64 _, [%0];"
                    :: "r"(ra) : "memory");
            }
        } else {
            float* hout = (t & 1) ? h0buf : h1buf;
            __stcg(hout + bglob * 512 + u0 + uu, hn);
            __threadfence();
            __syncthreads();
            if (tid == 0) atomicAdd(myctr, 1u);
        }

        // out write off the critical path
        outp[(size_t)t * 512] = hn;
    }
}

// ============================================================================
extern "C" void kernel_launch(void* const* d_in, const int* in_sizes, int n_in,
                              void* d_out, int out_size) {
    const float* x    = (const float*)d_in[0];   // [64,1024,512]
    const float* W    = (const float*)d_in[1];   // [512,1536]
    const float* R    = (const float*)d_in[2];   // [512,1536]
    const float* bias = (const float*)d_in[3];   // [2,1536]
    float* out = (float*)d_out;

    float *xw_ptr, *h0_ptr, *h1_ptr;
    unsigned* ctr_ptr;
    cudaGetSymbolAddress((void**)&xw_ptr, g_xw);
    cudaGetSymbolAddress((void**)&h0_ptr, g_h0);
    cudaGetSymbolAddress((void**)&h1_ptr, g_h1);
    cudaGetSymbolAddress((void**)&ctr_ptr, g_ctr);

    cudaMemsetAsync(h0_ptr, 0, 64 * 512 * sizeof(float));
    cudaMemsetAsync(ctr_ptr, 0, 8 * 32 * sizeof(unsigned));

    dim3 g1(1536 / P1_BN, 65536 / P1_BM);
    gemm_xw_kernel<<<g1, 256>>>(x, W, bias, xw_ptr);

    // ---- phase 2: dynamic smem opt-in, then try 16-CTA clusters ----
    cudaFuncSetAttribute(gru_seq_kernel,
                         cudaFuncAttributeMaxDynamicSharedMemorySize, SM2_BYTES);
    cudaFuncSetAttribute(gru_seq_kernel,
                         cudaFuncAttributeNonPortableClusterSizeAllowed, 1);

    cudaLaunchConfig_t cfg = {};
    cfg.gridDim = dim3(NB2, 1, 1);
    cfg.blockDim = dim3(256, 1, 1);
    cfg.dynamicSmemBytes = SM2_BYTES;
    cudaLaunchAttribute attrs[1];
    attrs[0].id = cudaLaunchAttributeClusterDimension;
    attrs[0].val.clusterDim = {16, 1, 1};
    cfg.attrs = attrs;
    cfg.numAttrs = 1;

    int nclusters = 0;
    cudaError_t qe = cudaOccupancyMaxActiveClusters(&nclusters, gru_seq_kernel, &cfg);
    int use_cluster = (qe == cudaSuccess && nclusters >= 8) ? 1 : 0;
    if (!use_cluster) (void)cudaGetLastError();

    if (use_cluster) {
        cudaError_t le = cudaLaunchKernelEx(&cfg, gru_seq_kernel,
                                            (const float*)xw_ptr, R, bias, out,
                                            h0_ptr, h1_ptr, ctr_ptr, 1);
        if (le != cudaSuccess) {
            (void)cudaGetLastError();
            use_cluster = 0;
        }
    }
    if (!use_cluster) {
        gru_seq_kernel<<<NB2, 256, SM2_BYTES>>>(xw_ptr, R, bias, out,
                                                h0_ptr, h1_ptr, ctr_ptr, 0);
    }
}

// round 7
// speedup vs baseline: 1.0242x; 1.0242x over previous
#include <cuda_runtime.h>
#include <cuda_bf16.h>
#include <cstdint>

typedef unsigned long long ull;

// ---------------- scratch (device globals: allocation-free) ----------------
__device__ float g_xw[(size_t)64 * 1024 * 1536];   // 402 MB input projections
__device__ float g_h0[64 * 512];
__device__ float g_h1[64 * 512];
__device__ unsigned g_ctr[8 * 32];                 // per-bg counters, 128B apart

// ---------------- f32x2 helpers ----------------
__device__ __forceinline__ void fma2(ull& d, ull a, ull b) {
    asm("fma.rn.f32x2 %0, %1, %2, %0;" : "+l"(d) : "l"(a), "l"(b));
}
__device__ __forceinline__ ull splat2(float x) {
    ull r; asm("mov.b64 %0, {%1, %1};" : "=l"(r) : "f"(x)); return r;
}
__device__ __forceinline__ ull pack2(float x, float y) {
    ull r; asm("mov.b64 %0, {%1, %2};" : "=l"(r) : "f"(x), "f"(y)); return r;
}
__device__ __forceinline__ void f4_to_u2(float4 v, ull& a, ull& b) {
    asm("mov.b64 %0, {%1, %2};" : "=l"(a) : "f"(v.x), "f"(v.y));
    asm("mov.b64 %0, {%1, %2};" : "=l"(b) : "f"(v.z), "f"(v.w));
}
__device__ __forceinline__ float2 unpk(ull v) {
    float2 r; asm("mov.b64 {%0, %1}, %2;" : "=f"(r.x), "=f"(r.y) : "l"(v)); return r;
}

__device__ __forceinline__ float sigf(float x) {
    return __fdividef(1.0f, 1.0f + __expf(-x));
}
__device__ __forceinline__ float tanh_acc(float x) {
    float ax = fabsf(x);
    float e = __expf(-2.0f * ax);
    float r = __fdividef(1.0f - e, 1.0f + e);
    return copysignf(r, x);
}

// ============================================================================
// Phase 1: xw = x @ W + b_in    (M=65536, K=512, N=1536), f32x2 SGEMM
// ============================================================================
#define P1_BM 128
#define P1_BN 256
#define P1_BK 16

__global__ void __launch_bounds__(256, 1) gemm_xw_kernel(
    const float* __restrict__ A,
    const float* __restrict__ W,
    const float* __restrict__ bias,
    float* __restrict__ C)
{
    __shared__ float As[P1_BK * (P1_BM + 4)];
    __shared__ float Bs[P1_BK * P1_BN];

    const int tid = threadIdx.x;
    const int tx = tid & 15;
    const int ty = tid >> 4;
    const int bm = blockIdx.y * P1_BM;
    const int bn = blockIdx.x * P1_BN;

    ull acc[8][8];
#pragma unroll
    for (int m = 0; m < 8; m++)
#pragma unroll
        for (int g = 0; g < 8; g++) acc[m][g] = 0ull;

    for (int kk = 0; kk < 512; kk += P1_BK) {
#pragma unroll
        for (int i = 0; i < 2; i++) {
            int s = tid + i * 256;
            int m = s >> 2;
            int kq = (s & 3) << 2;
            float4 v = *(const float4*)(A + (size_t)(bm + m) * 512 + kk + kq);
            As[(kq + 0) * (P1_BM + 4) + m] = v.x;
            As[(kq + 1) * (P1_BM + 4) + m] = v.y;
            As[(kq + 2) * (P1_BM + 4) + m] = v.z;
            As[(kq + 3) * (P1_BM + 4) + m] = v.w;
        }
#pragma unroll
        for (int i = 0; i < 4; i++) {
            int s = tid + i * 256;
            int k = s >> 6;
            int n4 = (s & 63) << 2;
            float4 v = *(const float4*)(W + (size_t)(kk + k) * 1536 + bn + n4);
            *(float4*)(Bs + k * P1_BN + n4) = v;
        }
        __syncthreads();

#pragma unroll
        for (int k = 0; k < P1_BK; k++) {
            float4 a0 = *(const float4*)(As + k * (P1_BM + 4) + ty * 8);
            float4 a1 = *(const float4*)(As + k * (P1_BM + 4) + ty * 8 + 4);
            ull bp[8];
#pragma unroll
            for (int g = 0; g < 4; g++) {
                float4 b4 = *(const float4*)(Bs + k * P1_BN + tx * 4 + 64 * g);
                f4_to_u2(b4, bp[2 * g], bp[2 * g + 1]);
            }
            float am[8] = {a0.x, a0.y, a0.z, a0.w, a1.x, a1.y, a1.z, a1.w};
#pragma unroll
            for (int m = 0; m < 8; m++) {
                ull as = splat2(am[m]);
#pragma unroll
                for (int g = 0; g < 8; g++) fma2(acc[m][g], as, bp[g]);
            }
        }
        __syncthreads();
    }

    float4 bi[4];
#pragma unroll
    for (int g = 0; g < 4; g++)
        bi[g] = *(const float4*)(bias + bn + tx * 4 + 64 * g);
#pragma unroll
    for (int m = 0; m < 8; m++) {
        float* crow = C + (size_t)(bm + ty * 8 + m) * 1536;
#pragma unroll
        for (int g = 0; g < 4; g++) {
            float2 p0 = unpk(acc[m][2 * g]);
            float2 p1 = unpk(acc[m][2 * g + 1]);
            float4 o;
            o.x = p0.x + bi[g].x; o.y = p0.y + bi[g].y;
            o.z = p1.x + bi[g].z; o.w = p1.y + bi[g].w;
            *(float4*)(crow + bn + tx * 4 + 64 * g) = o;
        }
    }
}

// ============================================================================
// Phase 2 v2: 256 CTAs = 8 bg x 32 ug, 2 CTAs/SM (stall hiding).
//   CTA = 8 batches x 16 units. warp = 64-k chunk, lane = (unit, k-half).
//   R in regs: 48 ull/thread. k-half partials merged via shfl_down(16).
// ============================================================================
#define V2_NB 256

__global__ void __launch_bounds__(256, 2) gru_seq_v2(
    const float* __restrict__ xw,    // [65536, 1536]
    const float* __restrict__ rk,    // [512, 1536]
    const float* __restrict__ bias,  // [2, 1536]
    float* __restrict__ out,         // [64, 1024, 512]
    float* __restrict__ h0buf,
    float* __restrict__ h1buf,
    unsigned* __restrict__ ctr)
{
    __shared__ float hs[8 * 512];        // 16 KB
    __shared__ float red[8 * 16 * 25];   // 12.8 KB (pad 25, coprime 32)
    __shared__ float sbias[48];

    const int tid = threadIdx.x;
    const int bgid = blockIdx.x >> 5;    // 0..7
    const int ugid = blockIdx.x & 31;    // 0..31
    const int u0 = ugid * 16;
    const int b0 = bgid * 8;

    const int w = tid >> 5;              // warp: 64-k chunk
    const int lane = tid & 31;
    const int uu = lane & 15;            // unit within group
    const int kh = lane >> 4;            // k-half (32 k)
    const int kbase = w * 64 + kh * 32;

    // ---- R slice: unit u0+uu, gates z/r/h, k in [kbase, kbase+32) ----
    ull Rz[16], Rr[16], Rh[16];
    {
        const float* rbase = rk + u0 + uu;
#pragma unroll
        for (int i = 0; i < 16; i++) {
            const float* r0 = rbase + (size_t)(kbase + 2 * i) * 1536;
            const float* r1 = r0 + 1536;
            Rz[i] = pack2(r0[0],    r1[0]);
            Rr[i] = pack2(r0[512],  r1[512]);
            Rh[i] = pack2(r0[1024], r1[1024]);
        }
    }
    if (tid < 48) {
        int u = tid / 3, g = tid - u * 3;
        sbias[u * 3 + g] = bias[1536 + g * 512 + u0 + u];
    }
    __syncthreads();

    // epilogue role (tid < 128): batch eb, unit eu
    const int eb = tid >> 4;
    const int eu = tid & 15;
    const float* xwp = xw + (size_t)(b0 + eb) * 1024 * 1536 + u0 + eu;
    float* outp = out + (size_t)(b0 + eb) * 524288 + u0 + eu;
    unsigned* myctr = ctr + bgid * 32;

    float hn_prev = 0.0f;

    for (int t = 0; t < 1024; t++) {
        // prefetch gate inputs (independent of h)
        float xz = 0.f, xr = 0.f, xh = 0.f;
        if (tid < 128) {
            const float* xr_ = xwp + (size_t)t * 1536;
            xz = __ldg(xr_);
            xr = __ldg(xr_ + 512);
            xh = __ldg(xr_ + 1024);
        }

        if (t > 0) {
            if (tid == 0) {
                unsigned target = (unsigned)(32 * t);
                unsigned v;
                do {
                    asm volatile("ld.acquire.gpu.global.u32 %0, [%1];"
                                 : "=r"(v) : "l"(myctr) : "memory");
                } while (v < target);
            }
            __syncthreads();
        }

        // ---- stage h: 8 batches x 512 = 1024 float4, 4/thread ----
        const float* hin = (t & 1) ? h1buf : h0buf;
        const float4* hsrc = (const float4*)(hin + b0 * 512);
#pragma unroll
        for (int i = 0; i < 4; i++) {
            int s = tid + i * 256;
            ((float4*)hs)[s] = __ldcg(hsrc + s);
        }
        __syncthreads();

        // ---- GEMM partials: (w, kh) covers k in [kbase, kbase+32) ----
#pragma unroll 1
        for (int b = 0; b < 8; b++) {
            ull az = 0ull, ar = 0ull, ah = 0ull;
            const float4* hp = (const float4*)(hs + b * 512 + kbase);
#pragma unroll
            for (int q = 0; q < 8; q++) {
                float4 h4 = hp[q];
                ull h01, h23;
                f4_to_u2(h4, h01, h23);
                fma2(az, h01, Rz[2 * q]); fma2(az, h23, Rz[2 * q + 1]);
                fma2(ar, h01, Rr[2 * q]); fma2(ar, h23, Rr[2 * q + 1]);
                fma2(ah, h01, Rh[2 * q]); fma2(ah, h23, Rh[2 * q + 1]);
            }
            float2 p;
            p = unpk(az); float vz = p.x + p.y;
            p = unpk(ar); float vr = p.x + p.y;
            p = unpk(ah); float vh = p.x + p.y;
            vz += __shfl_down_sync(0xffffffffu, vz, 16);
            vr += __shfl_down_sync(0xffffffffu, vr, 16);
            vh += __shfl_down_sync(0xffffffffu, vh, 16);
            if (kh == 0) {
                float* rb = red + (b * 16 + uu) * 25 + w * 3;
                rb[0] = vz; rb[1] = vr; rb[2] = vh;
            }
        }
        __syncthreads();

        // ---- gates: tid<128, thread = (batch eb, unit eu) ----
        float hn = 0.f;
        if (tid < 128) {
            float rz = sbias[eu * 3 + 0];
            float rr = sbias[eu * 3 + 1];
            float rh = sbias[eu * 3 + 2];
            const float* rb = red + (eb * 16 + eu) * 25;
#pragma unroll
            for (int s = 0; s < 8; s++) {
                rz += rb[s * 3 + 0];
                rr += rb[s * 3 + 1];
                rh += rb[s * 3 + 2];
            }
            float z  = sigf(xz + rz);
            float r  = sigf(xr + rr);
            float hh = tanh_acc(xh + r * rh);
            hn = z * hn_prev + (1.0f - z) * hh;
            hn_prev = hn;
            float* hout = (t & 1) ? h0buf : h1buf;
            __stcg(hout + (b0 + eb) * 512 + u0 + eu, hn);
        }
        __syncthreads();
        if (tid == 0) {
            asm volatile("red.release.gpu.global.add.u32 [%0], %1;"
                         :: "l"(myctr), "r"(1u) : "memory");
        }
        if (tid < 128) outp[(size_t)t * 512] = hn;
    }
}

// ============================================================================
// Phase 2 v1 (fallback): proven 128-CTA config (R4 counter path).
// ============================================================================
#define NB2 128

__global__ void __launch_bounds__(256, 1) gru_seq_v1(
    const float* __restrict__ xw,
    const float* __restrict__ rk,
    const float* __restrict__ bias,
    float* __restrict__ out,
    float* __restrict__ h0buf,
    float* __restrict__ h1buf,
    unsigned* __restrict__ ctr)
{
    __shared__ float hs[8 * 512];
    __shared__ float red[256 * 25];

    const int tid = threadIdx.x;
    const int bgid = blockIdx.x >> 4;
    const int ugid = blockIdx.x & 15;
    const int u0 = ugid * 32;
    const int b0 = bgid * 8;

    const int w  = tid >> 5;
    const int uu = tid & 31;

    ull Rz[32], Rr[32], Rh[32];
    {
        const float* rbase = rk + u0 + uu;
#pragma unroll
        for (int i = 0; i < 32; i++) {
            int k = w * 64 + 2 * i;
            const float* r0 = rbase + (size_t)k * 1536;
            const float* r1 = r0 + 1536;
            Rz[i] = pack2(r0[0],    r1[0]);
            Rr[i] = pack2(r0[512],  r1[512]);
            Rh[i] = pack2(r0[1024], r1[1024]);
        }
    }
    const float bz  = bias[1536 + u0 + uu];
    const float brr = bias[1536 + 512 + u0 + uu];
    const float bh  = bias[1536 + 1024 + u0 + uu];

    const int bglob = b0 + w;
    const float* xwp = xw + (size_t)bglob * 1024 * 1536 + u0 + uu;
    float* outp = out + (size_t)bglob * 524288 + u0 + uu;
    unsigned* myctr = ctr + bgid * 32;

    float hn_prev = 0.0f;

    for (int t = 0; t < 1024; t++) {
        const float* xr_ = xwp + (size_t)t * 1536;
        float xz = __ldg(xr_);
        float xr = __ldg(xr_ + 512);
        float xh = __ldg(xr_ + 1024);

        const float* hin = (t & 1) ? h1buf : h0buf;
        if (t > 0) {
            if (tid == 0) {
                unsigned target = (unsigned)(16 * t);
                unsigned v;
                do {
                    asm volatile("ld.acquire.gpu.global.u32 %0, [%1];"
                                 : "=r"(v) : "l"(myctr) : "memory");
                } while (v < target);
            }
            __syncthreads();
        }
#pragma unroll
        for (int i = 0; i < 4; i++) {
            int s = i * 32 + uu;
            int b = s >> 4;
            int j4 = s & 15;
            float4 v = __ldcg((const float4*)(hin + (b0 + b) * 512 + w * 64) + j4);
            *(float4*)(hs + b * 512 + w * 64 + j4 * 4) = v;
        }
        __syncwarp();

#pragma unroll 1
        for (int b = 0; b < 8; b++) {
            ull az = 0ull, ar = 0ull, ah = 0ull;
            const float4* hp = (const float4*)(hs + b * 512 + w * 64);
#pragma unroll
            for (int q = 0; q < 16; q++) {
                float4 h4 = hp[q];
                ull h01, h23;
                f4_to_u2(h4, h01, h23);
                fma2(az, h01, Rz[2 * q]); fma2(az, h23, Rz[2 * q + 1]);
                fma2(ar, h01, Rr[2 * q]); fma2(ar, h23, Rr[2 * q + 1]);
                fma2(ah, h01, Rh[2 * q]); fma2(ah, h23, Rh[2 * q + 1]);
            }
            float2 pz = unpk(az), pr = unpk(ar), ph = unpk(ah);
            float* rb = red + (b * 32 + uu) * 25 + w * 3;
            rb[0] = pz.x + pz.y;
            rb[1] = pr.x + pr.y;
            rb[2] = ph.x + ph.y;
        }
        __syncthreads();

        float rz = bz, rr = brr, rh = bh;
        const float* rb = red + (w * 32 + uu) * 25;
#pragma unroll
        for (int s = 0; s < 8; s++) {
            rz += rb[s * 3 + 0];
            rr += rb[s * 3 + 1];
            rh += rb[s * 3 + 2];
        }
        float z  = sigf(xz + rz);
        float r  = sigf(xr + rr);
        float hh = tanh_acc(xh + r * rh);
        float hn = z * hn_prev + (1.0f - z) * hh;
        hn_prev = hn;

        float* hout = (t & 1) ? h0buf : h1buf;
        __stcg(hout + bglob * 512 + u0 + uu, hn);
        __threadfence();
        __syncthreads();
        if (tid == 0) atomicAdd(myctr, 1u);

        outp[(size_t)t * 512] = hn;
    }
}

// ============================================================================
extern "C" void kernel_launch(void* const* d_in, const int* in_sizes, int n_in,
                              void* d_out, int out_size) {
    const float* x    = (const float*)d_in[0];
    const float* W    = (const float*)d_in[1];
    const float* R    = (const float*)d_in[2];
    const float* bias = (const float*)d_in[3];
    float* out = (float*)d_out;

    float *xw_ptr, *h0_ptr, *h1_ptr;
    unsigned* ctr_ptr;
    cudaGetSymbolAddress((void**)&xw_ptr, g_xw);
    cudaGetSymbolAddress((void**)&h0_ptr, g_h0);
    cudaGetSymbolAddress((void**)&h1_ptr, g_h1);
    cudaGetSymbolAddress((void**)&ctr_ptr, g_ctr);

    cudaMemsetAsync(h0_ptr, 0, 64 * 512 * sizeof(float));
    cudaMemsetAsync(ctr_ptr, 0, 8 * 32 * sizeof(unsigned));

    dim3 g1(1536 / P1_BN, 65536 / P1_BM);
    gemm_xw_kernel<<<g1, 256>>>(x, W, bias, xw_ptr);

    // v2 requires 2 CTAs/SM resident (256 CTAs on >=128 SMs). Verify, else v1.
    int occ = 0;
    cudaError_t qe = cudaOccupancyMaxActiveBlocksPerMultiprocessor(
        &occ, gru_seq_v2, 256, 0);
    int nsm = 0;
    cudaDeviceGetAttribute(&nsm, cudaDevAttrMultiProcessorCount, 0);
    if (qe == cudaSuccess && occ >= 2 && nsm * 2 >= V2_NB) {
        gru_seq_v2<<<V2_NB, 256>>>(xw_ptr, R, bias, out, h0_ptr, h1_ptr, ctr_ptr);
    } else {
        (void)cudaGetLastError();
        gru_seq_v1<<<NB2, 256>>>(xw_ptr, R, bias, out, h0_ptr, h1_ptr, ctr_ptr);
    }
}